// round 11
// baseline (speedup 1.0000x reference)
#include <cuda_runtime.h>

// Problem shapes (fixed by the dataset)
constexpr int B  = 8;
constexpr int H  = 512, W  = 512;
constexpr int HO = 1024, WO = 1024;
constexpr int FPY = 514;             // padded rows: y coords -1..512
constexpr int FPX = 516;             // padded row stride (514 valid + 2 pad, float4-aligned)
constexpr int TPR = 129;             // fix col-groups per row (129*4 = 516)
constexpr int NPIX = B * HO * WO;    // 8388608 output pixels
constexpr int NQUAD = NPIX / 4;      // 2097152 output quads
constexpr int NFIXT = B * FPY * TPR; // 530448 fix work items (4 px each)

constexpr int SCTAS = 888;           // 6 CTAs/SM -> all co-resident (required for barrier)
constexpr int STH   = 256;
constexpr int NT    = SCTAS * STH;   // 227328 threads

// Precomputed "fixed" depth map, padded domain. 8*514*516*4 B = 8.49 MB (L2-resident).
__device__ float4 g_fix4[B * FPY * (FPX / 4)];

// Device-wide barrier state (sense-reversing; self-resets each use, so it is
// safe across graph replays: count returns to 0, generation just increments).
__device__ unsigned g_bar_count = 0;
__device__ unsigned g_bar_gen   = 0;

// Load 6 input floats covering columns [px0-2, px0+3] of `row` (0 if OOB).
__device__ __forceinline__ void load_row6(const float* __restrict__ img, int row,
                                          int px0, float v[6]) {
    if ((unsigned)row >= (unsigned)H) {
        v[0] = v[1] = v[2] = v[3] = v[4] = v[5] = 0.0f;
        return;
    }
    const float* rp = img + row * W;
    if (px0 >= 4 && px0 <= 508) {
        float4 a = *(const float4*)(rp + px0 - 4);
        float4 b = *(const float4*)(rp + px0);
        v[0] = a.z; v[1] = a.w;
        v[2] = b.x; v[3] = b.y; v[4] = b.z; v[5] = b.w;
    } else {
#pragma unroll
        for (int i = 0; i < 6; i++) {
            int c = px0 - 2 + i;
            v[i] = ((unsigned)c < (unsigned)W) ? __ldg(rp + c) : 0.0f;
        }
    }
}

// Fix one work item: 4 consecutive padded pixels. First-valid among 9 offsets,
// reference order: (0,0), (-1,-1),(-1,0),(-1,1),(0,-1),(0,1),(1,-1),(1,0),(1,1)
__device__ __forceinline__ void fix_item(const float* __restrict__ depth, int idx) {
    int b  = idx / (FPY * TPR);
    int r  = idx - b * (FPY * TPR);
    int py = r / TPR;
    int t  = r - py * TPR;
    int px0 = t * 4;
    int y   = py - 1;

    const float* img = depth + b * (H * W);

    float m1[6], r0[6], p1[6];
    load_row6(img, y - 1, px0, m1);
    load_row6(img, y,     px0, r0);
    load_row6(img, y + 1, px0, p1);

    float4 o;
    float* op = &o.x;
#pragma unroll
    for (int j = 0; j < 4; j++) {
        float c[9] = { r0[j + 1],
                       m1[j], m1[j + 1], m1[j + 2],
                       r0[j],            r0[j + 2],
                       p1[j], p1[j + 1], p1[j + 2] };
        float v = 0.0f;
#pragma unroll
        for (int k = 8; k >= 0; k--) {
            if (c[k] != 0.0f) v = c[k];      // first-valid via reverse last-write
        }
        op[j] = v;
    }
    g_fix4[(b * FPY + py) * (FPX / 4) + t] = o;
}

// 4 independent gathers for quad q; grid values ga,gb.
__device__ __forceinline__ void do_quad(int q, float4 ga, float4 gb,
                                        float4* __restrict__ out) {
    int b = q >> 18;                          // quads never span batches (HO*WO = 1<<20)
    const float* fixp = (const float*)g_fix4 + b * (FPY * FPX);
    float gx[4] = {ga.x, ga.z, gb.x, gb.z};
    float gy[4] = {ga.y, ga.w, gb.y, gb.w};
    float v[4];
#pragma unroll
    for (int i = 0; i < 4; i++) {
        // ((g+1)*0.5)*511 == round_fp32(g+1) * 255.5 exactly (×0.5 exact);
        // __float2int_rn = ties-to-even = jnp.round
        float xf = __fmul_rn(__fadd_rn(gx[i], 1.0f), 255.5f);
        float yf = __fmul_rn(__fadd_rn(gy[i], 1.0f), 255.5f);
        int ix = __float2int_rn(xf) + 1;      // padded coords
        int iy = __float2int_rn(yf) + 1;
        bool inb = ((unsigned)ix < 514u) & ((unsigned)iy < 514u);
        v[i] = inb ? __ldg(fixp + iy * FPX + ix) : 0.0f;
    }
    float4 o = {v[0], v[1], v[2], v[3]};
    __stcs(out + q, o);
}

// Fused persistent kernel: fix phase -> device-wide barrier -> sample phase.
// __launch_bounds__(256, 6): regs capped so all 888 CTAs are guaranteed
// co-resident (6/SM * 148 = 888) — required for the spin barrier.
__global__ void __launch_bounds__(STH, 6)
fused_kernel(const float* __restrict__ depth,
             const float4* __restrict__ grid,
             float4* __restrict__ out) {
    int tid0 = blockIdx.x * STH + threadIdx.x;

    // ---- phase A: build fix map ----
    for (int idx = tid0; idx < NFIXT; idx += NT)
        fix_item(depth, idx);

    // ---- device-wide barrier (sense-reversing, self-resetting) ----
    __threadfence();                       // g_fix4 writes visible GPU-wide
    __syncthreads();
    if (threadIdx.x == 0) {
        unsigned my_gen = atomicAdd(&g_bar_gen, 0u);   // read current generation
        unsigned prev   = atomicAdd(&g_bar_count, 1u); // arrive
        if (prev == SCTAS - 1) {
            g_bar_count = 0;               // all arrived: reset for next use
            __threadfence();
            atomicAdd(&g_bar_gen, 1u);     // release
        } else {
            while (atomicAdd(&g_bar_gen, 0u) == my_gen) { }
        }
        __threadfence();
    }
    __syncthreads();

    // ---- phase B: sample (R4-best shape: grid-stride, depth-1 prefetch) ----
    int q = tid0;
    if (q >= NQUAD) return;

    float4 ga = __ldcs(grid + 2 * q);
    float4 gb = __ldcs(grid + 2 * q + 1);

    int qn = q + NT;
    while (qn < NQUAD) {
        float4 na = __ldcs(grid + 2 * qn);     // prefetch next (overlaps gathers)
        float4 nb = __ldcs(grid + 2 * qn + 1);
        do_quad(q, ga, gb, out);
        q = qn; qn += NT;
        ga = na; gb = nb;
    }
    do_quad(q, ga, gb, out);
}

extern "C" void kernel_launch(void* const* d_in, const int* in_sizes, int n_in,
                              void* d_out, int out_size) {
    const float*  depth = (const float*)d_in[0];   // (B,1,H,W) f32
    const float4* grid  = (const float4*)d_in[1];  // (B,Ho,Wo,2) f32 as float4
    float4*       out   = (float4*)d_out;          // (B,1,Ho,Wo) f32 as float4

    fused_kernel<<<SCTAS, STH>>>(depth, grid, out);
}